// round 11
// baseline (speedup 1.0000x reference)
#include <cuda_runtime.h>
#include <cuda_fp16.h>
#include <cstdint>

// ---------------- problem constants ----------------
#define MTOT 4096
#define NTOT 2048
#define KTOT 2048
#define BM   128
#define BN   128
#define BK   32
#define STAGES 4
#define KSTEPS (KTOT / BK)          // 64
#define THREADS 256

// fp16 smem stage row: 32 halves = 64B, permuted so each thread's fragment is LDS.128
#define ROWB 64
#define ASTG (BM * ROWB)            // 8192 bytes per stage (A or B)

// ---------------- smem layout (bytes) ----------------
#define SM_BIAS 0
#define SM_GNW  512
#define SM_GNB  1024
#define SM_A    2048
#define SM_B    (SM_A + STAGES * ASTG)            // 34816
#define SMEM_TOTAL (SM_B + STAGES * ASTG)         // 67584 (66KB)
#define B_OFF (SM_B - SM_A)                       // 32768

// ---------------- fp16, fragment-permuted scratch ----------------
__device__ __half g_xsh[(size_t)MTOT * KTOT];   // 16 MB
__device__ __half g_wsh[(size_t)NTOT * KTOT];   //  8 MB

// ---------------- PTX helpers ----------------
__device__ __forceinline__ uint32_t smem_u32(const void* p) {
    uint32_t a;
    asm("{ .reg .u64 t; cvta.to.shared.u64 t, %1; cvt.u32.u64 %0, t; }"
        : "=r"(a) : "l"(p));
    return a;
}

// cp.async with compile-time byte offsets on BOTH addresses
#define CP_A16I(smreg, gptr, smimm, gimm) \
    asm volatile("cp.async.cg.shared.global [%0+%2], [%1+%3], 16;" \
                 :: "r"(smreg), "l"(gptr), "n"(smimm), "n"(gimm) : "memory")
#define CP_COMMIT() asm volatile("cp.async.commit_group;" ::: "memory")
#define CP_WAIT(n)  asm volatile("cp.async.wait_group %0;" :: "n"(n) : "memory")

// LDS.128 with compile-time byte offset (imm MUST be a literal-constant expression)
#define LDS128I(r0, r1, r2, r3, base, imm) \
    asm volatile("ld.shared.v4.u32 {%0, %1, %2, %3}, [%4+%5];" \
                 : "=r"(r0), "=r"(r1), "=r"(r2), "=r"(r3) : "r"(base), "n"(imm))

__device__ __forceinline__ void mma_f16(float* c, uint32_t a0, uint32_t a1,
                                        uint32_t a2, uint32_t a3,
                                        uint32_t b0, uint32_t b1) {
    asm volatile(
        "mma.sync.aligned.m16n8k16.row.col.f32.f16.f16.f32 "
        "{%0,%1,%2,%3}, {%4,%5,%6,%7}, {%8,%9}, {%0,%1,%2,%3};"
        : "+f"(c[0]), "+f"(c[1]), "+f"(c[2]), "+f"(c[3])
        : "r"(a0), "r"(a1), "r"(a2), "r"(a3), "r"(b0), "r"(b1));
}

// ---------------- prepass: fp32 -> fp16 + fragment permutation ----------------
__global__ void __launch_bounds__(256)
prepass_kernel(const float* __restrict__ x, const float* __restrict__ w, int nunit) {
    int u = blockIdx.x * 256 + threadIdx.x;
    if (u >= nunit) return;
    int row = u >> 6;
    int uc  = u & 63;
    const float* src;
    __half* dst;
    if (row < MTOT) {
        src = x + (size_t)row * KTOT + uc * 32;
        dst = g_xsh + (size_t)row * KTOT + uc * 32;
    } else {
        src = w + (size_t)(row - MTOT) * KTOT + uc * 32;
        dst = g_wsh + (size_t)(row - MTOT) * KTOT + uc * 32;
    }
    float v[32];
#pragma unroll
    for (int i = 0; i < 8; i++) {
        float4 f = ((const float4*)src)[i];
        v[i * 4 + 0] = f.x; v[i * 4 + 1] = f.y; v[i * 4 + 2] = f.z; v[i * 4 + 3] = f.w;
    }
    __half h[32];
#pragma unroll
    for (int t4 = 0; t4 < 4; t4++) {
#pragma unroll
        for (int blk = 0; blk < 2; blk++) {
            int o = t4 * 8 + blk * 4;
            int c = blk * 16 + 2 * t4;
            h[o + 0] = __float2half_rn(v[c + 0]);
            h[o + 1] = __float2half_rn(v[c + 1]);
            h[o + 2] = __float2half_rn(v[c + 8]);
            h[o + 3] = __float2half_rn(v[c + 9]);
        }
    }
#pragma unroll
    for (int i = 0; i < 4; i++)
        ((uint4*)dst)[i] = ((const uint4*)h)[i];
}

// ---------------- kernel ----------------
__global__ void __launch_bounds__(THREADS, 1)
fused_linear_gn_ht_kernel(const __half* __restrict__ xs,
                          const __half* __restrict__ ws,
                          const float* __restrict__ bias,
                          const float* __restrict__ gnw,
                          const float* __restrict__ gnb,
                          float* __restrict__ out) {
    extern __shared__ char smem[];
    uint32_t sb = smem_u32(smem);
    int tid = threadIdx.x;
    int wid = tid >> 5, lid = tid & 31;
    int wm = wid >> 1, wn = wid & 1;           // warp grid 4 (M) x 2 (N)
    int gid = lid >> 2, tid4 = lid & 3;
    int bn = blockIdx.x, bm = blockIdx.y;

    float* bias_s = (float*)(smem + SM_BIAS);
    float* gnw_s  = (float*)(smem + SM_GNW);
    float* gnb_s  = (float*)(smem + SM_GNB);
    if (tid < BN) {
        bias_s[tid] = bias[bn * BN + tid];
        gnw_s[tid]  = gnw[bn * BN + tid];
        gnb_s[tid]  = gnb[bn * BN + tid];
    }

    // ---- minimal address state: 1 smem-dst reg, 2 global ptr regs, 2 frag base regs
    int rA = tid >> 2, cA = tid & 3;           // cp.async geometry, chunk q=tid
    uint32_t cpSm = sb + SM_A + (uint32_t)(rA * ROWB + cA * 16);
    const __half* aPtr = xs + (size_t)bm * BM * KTOT + (size_t)rA * KTOT + cA * 8;
    const __half* bPtr = ws + (size_t)bn * BN * KTOT + (size_t)rA * KTOT + cA * 8;
    // second chunk (row +64): global +64*KTOT*2 = 262144 bytes, smem +64*ROWB = 4096
#define GCH 262144
#define SCH 4096

    // prologue: stages 0..2
#define PRO(p) do {                                                   \
        CP_A16I(cpSm, aPtr, (p) * ASTG,           (p) * 64);          \
        CP_A16I(cpSm, aPtr, (p) * ASTG + SCH,     (p) * 64 + GCH);    \
        CP_A16I(cpSm, bPtr, (p) * ASTG + B_OFF,       (p) * 64);      \
        CP_A16I(cpSm, bPtr, (p) * ASTG + B_OFF + SCH, (p) * 64 + GCH);\
        CP_COMMIT();                                                  \
    } while (0)
    PRO(0); PRO(1); PRO(2);
#undef PRO
    aPtr += (STAGES - 1) * BK;
    bPtr += (STAGES - 1) * BK;

    float acc[2][8][4];
#pragma unroll
    for (int mi = 0; mi < 2; mi++)
#pragma unroll
        for (int ni = 0; ni < 8; ni++)
#pragma unroll
            for (int j = 0; j < 4; j++) acc[mi][ni][j] = 0.f;

    // fragment base addresses (2 registers; everything else immediate)
    uint32_t aBase = sb + SM_A + (uint32_t)((wm * 32 + gid) * ROWB + tid4 * 16);
    uint32_t bBase = sb + SM_B + (uint32_t)((wn * 64 + gid) * ROWB + tid4 * 16);

    // ---- fully expanded fragment loads (literal immediates only) ----
#define LD_FRAGS(S)                                                              \
        LDS128I(alo[0][0], alo[0][1], alo[0][2], alo[0][3], aBase,               \
                (S) * ASTG + 0 * 512);                                           \
        LDS128I(ahi[0][0], ahi[0][1], ahi[0][2], ahi[0][3], aBase,               \
                (S) * ASTG + 1 * 512);                                           \
        LDS128I(alo[1][0], alo[1][1], alo[1][2], alo[1][3], aBase,               \
                (S) * ASTG + 2 * 512);                                           \
        LDS128I(ahi[1][0], ahi[1][1], ahi[1][2], ahi[1][3], aBase,               \
                (S) * ASTG + 3 * 512);                                           \
        LDS128I(bfr[0][0], bfr[0][1], bfr[0][2], bfr[0][3], bBase,               \
                (S) * ASTG + 0 * 512);                                           \
        LDS128I(bfr[1][0], bfr[1][1], bfr[1][2], bfr[1][3], bBase,               \
                (S) * ASTG + 1 * 512);                                           \
        LDS128I(bfr[2][0], bfr[2][1], bfr[2][2], bfr[2][3], bBase,               \
                (S) * ASTG + 2 * 512);                                           \
        LDS128I(bfr[3][0], bfr[3][1], bfr[3][2], bfr[3][3], bBase,               \
                (S) * ASTG + 3 * 512);                                           \
        LDS128I(bfr[4][0], bfr[4][1], bfr[4][2], bfr[4][3], bBase,               \
                (S) * ASTG + 4 * 512);                                           \
        LDS128I(bfr[5][0], bfr[5][1], bfr[5][2], bfr[5][3], bBase,               \
                (S) * ASTG + 5 * 512);                                           \
        LDS128I(bfr[6][0], bfr[6][1], bfr[6][2], bfr[6][3], bBase,               \
                (S) * ASTG + 6 * 512);                                           \
        LDS128I(bfr[7][0], bfr[7][1], bfr[7][2], bfr[7][3], bBase,               \
                (S) * ASTG + 7 * 512);

#define KITER(S)                                                                 \
    do {                                                                         \
        CP_WAIT(STAGES - 2);                                                     \
        __syncthreads();                                                         \
        if (k0 + (S) + STAGES - 1 < KSTEPS) {                                    \
            constexpr int PS = ((S) + STAGES - 1) & (STAGES - 1);                \
            CP_A16I(cpSm, aPtr, PS * ASTG,           (S) * 64);                  \
            CP_A16I(cpSm, aPtr, PS * ASTG + SCH,     (S) * 64 + GCH);            \
            CP_A16I(cpSm, bPtr, PS * ASTG + B_OFF,       (S) * 64);              \
            CP_A16I(cpSm, bPtr, PS * ASTG + B_OFF + SCH, (S) * 64 + GCH);        \
        }                                                                        \
        CP_COMMIT();                                                             \
        uint32_t alo[2][4], ahi[2][4], bfr[8][4];                                \
        LD_FRAGS(S)                                                              \
        _Pragma("unroll")                                                        \
        for (int blk = 0; blk < 2; blk++)                                        \
            _Pragma("unroll")                                                    \
            for (int mi = 0; mi < 2; mi++)                                       \
                _Pragma("unroll")                                                \
                for (int ni = 0; ni < 8; ni++)                                   \
                    mma_f16(acc[mi][ni],                                         \
                            alo[mi][blk * 2 + 0], ahi[mi][blk * 2 + 0],          \
                            alo[mi][blk * 2 + 1], ahi[mi][blk * 2 + 1],          \
                            bfr[ni][blk * 2 + 0], bfr[ni][blk * 2 + 1]);         \
    } while (0)

    for (int k0 = 0; k0 < KSTEPS; k0 += STAGES) {
        KITER(0);
        KITER(1);
        KITER(2);
        KITER(3);
        aPtr += STAGES * BK;          // one bump per 4 k-steps
        bPtr += STAGES * BK;
    }
#undef KITER
#undef LD_FRAGS

    // ---------------- fused epilogue: bias + GroupNorm(64) + hardtanh ----------------
    int gcol = wn * 64;
    size_t gout = (size_t)bn * BN + gcol;

#pragma unroll
    for (int mi = 0; mi < 2; mi++) {
#pragma unroll
        for (int half = 0; half < 2; half++) {
            int row_l = wm * 32 + mi * 16 + half * 8 + gid;
            float sum = 0.f, ssq = 0.f;
            float v[8][2];
#pragma unroll
            for (int ni = 0; ni < 8; ni++) {
                int c = ni * 8 + 2 * tid4;
                float v0 = acc[mi][ni][half * 2 + 0] + bias_s[gcol + c + 0];
                float v1 = acc[mi][ni][half * 2 + 1] + bias_s[gcol + c + 1];
                v[ni][0] = v0; v[ni][1] = v1;
                sum += v0 + v1;
                ssq += v0 * v0 + v1 * v1;
            }
            sum += __shfl_xor_sync(0xffffffffu, sum, 1);
            ssq += __shfl_xor_sync(0xffffffffu, ssq, 1);
            sum += __shfl_xor_sync(0xffffffffu, sum, 2);
            ssq += __shfl_xor_sync(0xffffffffu, ssq, 2);

            float mean = sum * (1.f / 64.f);
            float var  = ssq * (1.f / 64.f) - mean * mean;
            float inv  = rsqrtf(var + 1e-5f);

            size_t orow = (size_t)(bm * BM + row_l) * NTOT + gout;
#pragma unroll
            for (int ni = 0; ni < 8; ni++) {
                int c = ni * 8 + 2 * tid4;
                float2 o;
                o.x = fminf(fmaxf((v[ni][0] - mean) * inv * gnw_s[gcol + c + 0]
                                  + gnb_s[gcol + c + 0], -1.f), 1.f);
                o.y = fminf(fmaxf((v[ni][1] - mean) * inv * gnw_s[gcol + c + 1]
                                  + gnb_s[gcol + c + 1], -1.f), 1.f);
                *(float2*)(out + orow + c) = o;
            }
        }
    }
}

// ---------------- launch ----------------
extern "C" void kernel_launch(void* const* d_in, const int* in_sizes, int n_in,
                              void* d_out, int out_size) {
    const float* x    = (const float*)d_in[0];
    const float* w    = (const float*)d_in[1];
    const float* bias = (const float*)d_in[2];
    const float* gnw  = (const float*)d_in[3];
    const float* gnb  = (const float*)d_in[4];
    float* out = (float*)d_out;

    static bool attr_done = false;
    if (!attr_done) {
        cudaFuncSetAttribute(fused_linear_gn_ht_kernel,
                             cudaFuncAttributeMaxDynamicSharedMemorySize, SMEM_TOTAL);
        attr_done = true;
    }

    __half* xs; __half* ws;
    cudaGetSymbolAddress((void**)&xs, g_xsh);
    cudaGetSymbolAddress((void**)&ws, g_wsh);

    int nunit = ((MTOT + NTOT) * KTOT) / 32;    // 393216
    prepass_kernel<<<(nunit + 255) / 256, 256>>>(x, w, nunit);

    dim3 grid(NTOT / BN, MTOT / BM);   // (16, 32) = 512 CTAs
    fused_linear_gn_ht_kernel<<<grid, THREADS, SMEM_TOTAL>>>(xs, ws, bias, gnw, gnb, out);
}

// round 12
// speedup vs baseline: 1.1503x; 1.1503x over previous
#include <cuda_runtime.h>
#include <cuda_fp16.h>
#include <cstdint>

// ---------------- problem constants ----------------
#define MTOT 4096
#define NTOT 2048
#define KTOT 2048
#define BM   256
#define BN   128
#define BK   32
#define STAGES 4
#define KSTEPS (KTOT / BK)          // 64
#define THREADS 256

// fp16 smem stage row: 32 halves = 64B, permuted so each thread's fragment is LDS.128
#define ROWB 64
#define ASTG_A (BM * ROWB)          // 16384 bytes per A stage
#define ASTG_B (BN * ROWB)          // 8192  bytes per B stage

// ---------------- smem layout (bytes) ----------------
#define SM_BIAS 0
#define SM_GNW  512
#define SM_GNB  1024
#define SM_A    2048
#define SM_B    (SM_A + STAGES * ASTG_A)          // 67584
#define SMEM_TOTAL (SM_B + STAGES * ASTG_B)       // 100352 (98KB), 1 CTA/SM

// ---------------- fp16, fragment-permuted scratch ----------------
__device__ __half g_xsh[(size_t)MTOT * KTOT];   // 16 MB
__device__ __half g_wsh[(size_t)NTOT * KTOT];   //  8 MB

// ---------------- PTX helpers ----------------
__device__ __forceinline__ uint32_t smem_u32(const void* p) {
    uint32_t a;
    asm("{ .reg .u64 t; cvta.to.shared.u64 t, %1; cvt.u32.u64 %0, t; }"
        : "=r"(a) : "l"(p));
    return a;
}

// cp.async with compile-time byte offsets on BOTH addresses
#define CP_A16I(smreg, gptr, smimm, gimm) \
    asm volatile("cp.async.cg.shared.global [%0+%2], [%1+%3], 16;" \
                 :: "r"(smreg), "l"(gptr), "n"(smimm), "n"(gimm) : "memory")
#define CP_COMMIT() asm volatile("cp.async.commit_group;" ::: "memory")
#define CP_WAIT(n)  asm volatile("cp.async.wait_group %0;" :: "n"(n) : "memory")

// LDS.128 with compile-time byte offset (imm MUST be a literal-constant expression)
#define LDS128I(r0, r1, r2, r3, base, imm) \
    asm volatile("ld.shared.v4.u32 {%0, %1, %2, %3}, [%4+%5];" \
                 : "=r"(r0), "=r"(r1), "=r"(r2), "=r"(r3) : "r"(base), "n"(imm))

__device__ __forceinline__ void mma_f16(float* c, uint32_t a0, uint32_t a1,
                                        uint32_t a2, uint32_t a3,
                                        uint32_t b0, uint32_t b1) {
    asm volatile(
        "mma.sync.aligned.m16n8k16.row.col.f32.f16.f16.f32 "
        "{%0,%1,%2,%3}, {%4,%5,%6,%7}, {%8,%9}, {%0,%1,%2,%3};"
        : "+f"(c[0]), "+f"(c[1]), "+f"(c[2]), "+f"(c[3])
        : "r"(a0), "r"(a1), "r"(a2), "r"(a3), "r"(b0), "r"(b1));
}

// ---------------- prepass: fp32 -> fp16 + fragment permutation ----------------
__global__ void __launch_bounds__(256)
prepass_kernel(const float* __restrict__ x, const float* __restrict__ w, int nunit) {
    int u = blockIdx.x * 256 + threadIdx.x;
    if (u >= nunit) return;
    int row = u >> 6;
    int uc  = u & 63;
    const float* src;
    __half* dst;
    if (row < MTOT) {
        src = x + (size_t)row * KTOT + uc * 32;
        dst = g_xsh + (size_t)row * KTOT + uc * 32;
    } else {
        src = w + (size_t)(row - MTOT) * KTOT + uc * 32;
        dst = g_wsh + (size_t)(row - MTOT) * KTOT + uc * 32;
    }
    float v[32];
#pragma unroll
    for (int i = 0; i < 8; i++) {
        float4 f = ((const float4*)src)[i];
        v[i * 4 + 0] = f.x; v[i * 4 + 1] = f.y; v[i * 4 + 2] = f.z; v[i * 4 + 3] = f.w;
    }
    __half h[32];
#pragma unroll
    for (int t4 = 0; t4 < 4; t4++) {
#pragma unroll
        for (int blk = 0; blk < 2; blk++) {
            int o = t4 * 8 + blk * 4;
            int c = blk * 16 + 2 * t4;
            h[o + 0] = __float2half_rn(v[c + 0]);
            h[o + 1] = __float2half_rn(v[c + 1]);
            h[o + 2] = __float2half_rn(v[c + 8]);
            h[o + 3] = __float2half_rn(v[c + 9]);
        }
    }
#pragma unroll
    for (int i = 0; i < 4; i++)
        ((uint4*)dst)[i] = ((const uint4*)h)[i];
}

// ---------------- kernel ----------------
__global__ void __launch_bounds__(THREADS, 1)
fused_linear_gn_ht_kernel(const __half* __restrict__ xs,
                          const __half* __restrict__ ws,
                          const float* __restrict__ bias,
                          const float* __restrict__ gnw,
                          const float* __restrict__ gnb,
                          float* __restrict__ out) {
    extern __shared__ char smem[];
    uint32_t sb = smem_u32(smem);
    int tid = threadIdx.x;
    int wid = tid >> 5, lid = tid & 31;
    int wm = wid >> 1, wn = wid & 1;           // warp grid 4 (M) x 2 (N), tile 64x64
    int gid = lid >> 2, tid4 = lid & 3;
    int bn = blockIdx.x, bm = blockIdx.y;

    float* bias_s = (float*)(smem + SM_BIAS);
    float* gnw_s  = (float*)(smem + SM_GNW);
    float* gnb_s  = (float*)(smem + SM_GNB);
    if (tid < BN) {
        bias_s[tid] = bias[bn * BN + tid];
        gnw_s[tid]  = gnw[bn * BN + tid];
        gnb_s[tid]  = gnb[bn * BN + tid];
    }

    // ---- cp.async geometry: r = tid>>2 (+64 per i), c = tid&3
    int rA = tid >> 2, cA = tid & 3;
    uint32_t cpA = sb + SM_A + (uint32_t)(rA * ROWB + cA * 16);
    uint32_t cpB = sb + SM_B + (uint32_t)(rA * ROWB + cA * 16);
    const __half* aPtr = xs + (size_t)bm * BM * KTOT + (size_t)rA * KTOT + cA * 8;
    const __half* bPtr = ws + (size_t)bn * BN * KTOT + (size_t)rA * KTOT + cA * 8;
    // +64 rows: global +64*KTOT*2 = 262144 bytes; smem +64*ROWB = 4096 bytes
#define GCH 262144
#define SCH 4096

    // prologue: stages 0..2 (A: 4 chunks/thread, B: 2 chunks/thread)
#define PRO(p) do {                                                       \
        CP_A16I(cpA, aPtr, (p) * ASTG_A + 0 * SCH, (p) * 64 + 0 * GCH);   \
        CP_A16I(cpA, aPtr, (p) * ASTG_A + 1 * SCH, (p) * 64 + 1 * GCH);   \
        CP_A16I(cpA, aPtr, (p) * ASTG_A + 2 * SCH, (p) * 64 + 2 * GCH);   \
        CP_A16I(cpA, aPtr, (p) * ASTG_A + 3 * SCH, (p) * 64 + 3 * GCH);   \
        CP_A16I(cpB, bPtr, (p) * ASTG_B + 0 * SCH, (p) * 64 + 0 * GCH);   \
        CP_A16I(cpB, bPtr, (p) * ASTG_B + 1 * SCH, (p) * 64 + 1 * GCH);   \
        CP_COMMIT();                                                      \
    } while (0)
    PRO(0); PRO(1); PRO(2);
#undef PRO
    aPtr += (STAGES - 1) * BK;
    bPtr += (STAGES - 1) * BK;

    float acc[4][8][4];
#pragma unroll
    for (int mi = 0; mi < 4; mi++)
#pragma unroll
        for (int ni = 0; ni < 8; ni++)
#pragma unroll
            for (int j = 0; j < 4; j++) acc[mi][ni][j] = 0.f;

    // fragment base addresses (2 registers; everything else immediate)
    uint32_t aBase = sb + SM_A + (uint32_t)((wm * 64 + gid) * ROWB + tid4 * 16);
    uint32_t bBase = sb + SM_B + (uint32_t)((wn * 64 + gid) * ROWB + tid4 * 16);

    // ---- fully expanded fragment loads (literal immediates only) ----
    // A: mi block = +16 rows = +1024B; hi row (+8) = +512B. B: ni block = +512B.
#define LD_FRAGS(S)                                                              \
        LDS128I(alo[0][0], alo[0][1], alo[0][2], alo[0][3], aBase,               \
                (S) * ASTG_A + 0 * 1024);                                        \
        LDS128I(ahi[0][0], ahi[0][1], ahi[0][2], ahi[0][3], aBase,               \
                (S) * ASTG_A + 0 * 1024 + 512);                                  \
        LDS128I(alo[1][0], alo[1][1], alo[1][2], alo[1][3], aBase,               \
                (S) * ASTG_A + 1 * 1024);                                        \
        LDS128I(ahi[1][0], ahi[1][1], ahi[1][2], ahi[1][3], aBase,               \
                (S) * ASTG_A + 1 * 1024 + 512);                                  \
        LDS128I(alo[2][0], alo[2][1], alo[2][2], alo[2][3], aBase,               \
                (S) * ASTG_A + 2 * 1024);                                        \
        LDS128I(ahi[2][0], ahi[2][1], ahi[2][2], ahi[2][3], aBase,               \
                (S) * ASTG_A + 2 * 1024 + 512);                                  \
        LDS128I(alo[3][0], alo[3][1], alo[3][2], alo[3][3], aBase,               \
                (S) * ASTG_A + 3 * 1024);                                        \
        LDS128I(ahi[3][0], ahi[3][1], ahi[3][2], ahi[3][3], aBase,               \
                (S) * ASTG_A + 3 * 1024 + 512);                                  \
        LDS128I(bfr[0][0], bfr[0][1], bfr[0][2], bfr[0][3], bBase,               \
                (S) * ASTG_B + 0 * 512);                                         \
        LDS128I(bfr[1][0], bfr[1][1], bfr[1][2], bfr[1][3], bBase,               \
                (S) * ASTG_B + 1 * 512);                                         \
        LDS128I(bfr[2][0], bfr[2][1], bfr[2][2], bfr[2][3], bBase,               \
                (S) * ASTG_B + 2 * 512);                                         \
        LDS128I(bfr[3][0], bfr[3][1], bfr[3][2], bfr[3][3], bBase,               \
                (S) * ASTG_B + 3 * 512);                                         \
        LDS128I(bfr[4][0], bfr[4][1], bfr[4][2], bfr[4][3], bBase,               \
                (S) * ASTG_B + 4 * 512);                                         \
        LDS128I(bfr[5][0], bfr[5][1], bfr[5][2], bfr[5][3], bBase,               \
                (S) * ASTG_B + 5 * 512);                                         \
        LDS128I(bfr[6][0], bfr[6][1], bfr[6][2], bfr[6][3], bBase,               \
                (S) * ASTG_B + 6 * 512);                                         \
        LDS128I(bfr[7][0], bfr[7][1], bfr[7][2], bfr[7][3], bBase,               \
                (S) * ASTG_B + 7 * 512);

#define KITER(S)                                                                 \
    do {                                                                         \
        CP_WAIT(STAGES - 2);                                                     \
        __syncthreads();                                                         \
        if (k0 + (S) + STAGES - 1 < KSTEPS) {                                    \
            constexpr int PS = ((S) + STAGES - 1) & (STAGES - 1);                \
            CP_A16I(cpA, aPtr, PS * ASTG_A + 0 * SCH, (S) * 64 + 0 * GCH);       \
            CP_A16I(cpA, aPtr, PS * ASTG_A + 1 * SCH, (S) * 64 + 1 * GCH);       \
            CP_A16I(cpA, aPtr, PS * ASTG_A + 2 * SCH, (S) * 64 + 2 * GCH);       \
            CP_A16I(cpA, aPtr, PS * ASTG_A + 3 * SCH, (S) * 64 + 3 * GCH);       \
            CP_A16I(cpB, bPtr, PS * ASTG_B + 0 * SCH, (S) * 64 + 0 * GCH);       \
            CP_A16I(cpB, bPtr, PS * ASTG_B + 1 * SCH, (S) * 64 + 1 * GCH);       \
        }                                                                        \
        CP_COMMIT();                                                             \
        uint32_t alo[4][4], ahi[4][4], bfr[8][4];                                \
        LD_FRAGS(S)                                                              \
        _Pragma("unroll")                                                        \
        for (int blk = 0; blk < 2; blk++)                                        \
            _Pragma("unroll")                                                    \
            for (int mi = 0; mi < 4; mi++)                                       \
                _Pragma("unroll")                                                \
                for (int ni = 0; ni < 8; ni++)                                   \
                    mma_f16(acc[mi][ni],                                         \
                            alo[mi][blk * 2 + 0], ahi[mi][blk * 2 + 0],          \
                            alo[mi][blk * 2 + 1], ahi[mi][blk * 2 + 1],          \
                            bfr[ni][blk * 2 + 0], bfr[ni][blk * 2 + 1]);         \
    } while (0)

    for (int k0 = 0; k0 < KSTEPS; k0 += STAGES) {
        KITER(0);
        KITER(1);
        KITER(2);
        KITER(3);
        aPtr += STAGES * BK;          // one bump per 4 k-steps
        bPtr += STAGES * BK;
    }
#undef KITER
#undef LD_FRAGS

    // ---------------- fused epilogue: bias + GroupNorm(64) + hardtanh ----------------
    // warp tile N=64 == exactly one group
    int gcol = wn * 64;
    size_t gout = (size_t)bn * BN + gcol;

#pragma unroll
    for (int mi = 0; mi < 4; mi++) {
#pragma unroll
        for (int half = 0; half < 2; half++) {
            int row_l = wm * 64 + mi * 16 + half * 8 + gid;
            float sum = 0.f, ssq = 0.f;
            float v[8][2];
#pragma unroll
            for (int ni = 0; ni < 8; ni++) {
                int c = ni * 8 + 2 * tid4;
                float v0 = acc[mi][ni][half * 2 + 0] + bias_s[gcol + c + 0];
                float v1 = acc[mi][ni][half * 2 + 1] + bias_s[gcol + c + 1];
                v[ni][0] = v0; v[ni][1] = v1;
                sum += v0 + v1;
                ssq += v0 * v0 + v1 * v1;
            }
            sum += __shfl_xor_sync(0xffffffffu, sum, 1);
            ssq += __shfl_xor_sync(0xffffffffu, ssq, 1);
            sum += __shfl_xor_sync(0xffffffffu, sum, 2);
            ssq += __shfl_xor_sync(0xffffffffu, ssq, 2);

            float mean = sum * (1.f / 64.f);
            float var  = ssq * (1.f / 64.f) - mean * mean;
            float inv  = rsqrtf(var + 1e-5f);

            size_t orow = (size_t)(bm * BM + row_l) * NTOT + gout;
#pragma unroll
            for (int ni = 0; ni < 8; ni++) {
                int c = ni * 8 + 2 * tid4;
                float2 o;
                o.x = fminf(fmaxf((v[ni][0] - mean) * inv * gnw_s[gcol + c + 0]
                                  + gnb_s[gcol + c + 0], -1.f), 1.f);
                o.y = fminf(fmaxf((v[ni][1] - mean) * inv * gnw_s[gcol + c + 1]
                                  + gnb_s[gcol + c + 1], -1.f), 1.f);
                *(float2*)(out + orow + c) = o;
            }
        }
    }
}

// ---------------- launch ----------------
extern "C" void kernel_launch(void* const* d_in, const int* in_sizes, int n_in,
                              void* d_out, int out_size) {
    const float* x    = (const float*)d_in[0];
    const float* w    = (const float*)d_in[1];
    const float* bias = (const float*)d_in[2];
    const float* gnw  = (const float*)d_in[3];
    const float* gnb  = (const float*)d_in[4];
    float* out = (float*)d_out;

    static bool attr_done = false;
    if (!attr_done) {
        cudaFuncSetAttribute(fused_linear_gn_ht_kernel,
                             cudaFuncAttributeMaxDynamicSharedMemorySize, SMEM_TOTAL);
        attr_done = true;
    }

    __half* xs; __half* ws;
    cudaGetSymbolAddress((void**)&xs, g_xsh);
    cudaGetSymbolAddress((void**)&ws, g_wsh);

    int nunit = ((MTOT + NTOT) * KTOT) / 32;    // 393216
    prepass_kernel<<<(nunit + 255) / 256, 256>>>(x, w, nunit);

    dim3 grid(NTOT / BN, MTOT / BM);   // (16, 16) = 256 CTAs
    fused_linear_gn_ht_kernel<<<grid, THREADS, SMEM_TOTAL>>>(xs, ws, bias, gnw, gnb, out);
}